// round 3
// baseline (speedup 1.0000x reference)
#include <cuda_runtime.h>
#include <cstdint>

#define Bsz 1024
#define Tt  128
#define Dd  64
#define Hh  256
#define MB  8
#define NT  512
#define GRID 128

typedef unsigned long long u64;

// transposed td_h_W: [k][c] (k in 0..63, c in 0..255), built by prologue kernel
__device__ float tdhT_g[Dd * Hh];

struct __align__(16) Smem {
    float hist[Hh * Dd];     // [k][j] (as given)            64 KB
    float tdxT[Dd * Dd];     // [k][j]                       16 KB
    float frT[Dd * Dd];      // [k][j]                       16 KB
    float wc[2 * Dd * Dd];   // [k][j]                       32 KB
    float hp[4 * 2 * Hh];    // h paired [p][k*2+par]         8 KB
    float cs[MB * Hh];       // c state                       8 KB
    float zp[4 * 2 * 4 * Hh];// gate acts [p][col*2+par]     32 KB (aliased as cpart in phase C)
    float xs[MB * Dd], ms[MB * Dd];
    float mp[4 * 2 * Dd], dp[4 * 2 * Dd];          // paired m, d
    float gxp[4 * 2 * Dd], alp[4 * 2 * Dd];        // paired gamma_x, alpha
    float xcp[4 * 2 * Dd], xhp[4 * 2 * Dd], ccp[4 * 2 * Dd];
    float tdh_b[Hh], tdx_b[Dd], hist_b[Dd], fr_b[Dd], wc_b[Dd], lstm_b[4 * Hh];
};

__device__ __forceinline__ u64 dup2(float w) {
    u64 r; asm("mov.b64 %0, {%1,%1};" : "=l"(r) : "f"(w)); return r;
}
__device__ __forceinline__ void upk2(u64 v, float& lo, float& hi) {
    asm("mov.b64 {%0,%1}, %2;" : "=f"(lo), "=f"(hi) : "l"(v));
}
__device__ __forceinline__ u64 fma2(u64 a, u64 b, u64 c) {
    u64 d; asm("fma.rn.f32x2 %0, %1, %2, %3;" : "=l"(d) : "l"(a), "l"(b), "l"(c)); return d;
}
__device__ __forceinline__ float sigf(float x) {
    return __fdividef(1.f, 1.f + __expf(-x));
}
__device__ __forceinline__ float tanhfast(float x) {
    return __fdividef(2.f, 1.f + __expf(-2.f * x)) - 1.f;
}

__global__ void transpose_tdh_kernel(const float* __restrict__ w) {
    int idx = blockIdx.x * 256 + threadIdx.x;   // 16384 elements
    int c = idx >> 6, k = idx & 63;
    tdhT_g[k * Hh + c] = w[idx];
}

__global__ void __launch_bounds__(NT, 1) rits_kernel(
    const float* __restrict__ values, const float* __restrict__ masks,
    const float* __restrict__ deltas,
    const float* __restrict__ tdhB,
    const float* __restrict__ tdxW, const float* __restrict__ tdxB,
    const float* __restrict__ histW, const float* __restrict__ histB,
    const float* __restrict__ frW, const float* __restrict__ frB,
    const float* __restrict__ wcW, const float* __restrict__ wcB,
    const float* __restrict__ lstmK, const float* __restrict__ lstmRK,
    const float* __restrict__ lstmB,
    const float* __restrict__ outW, const float* __restrict__ outB,
    float* __restrict__ yout, float* __restrict__ impout)
{
    extern __shared__ char smem_raw[];
    Smem& sm = *reinterpret_cast<Smem*>(smem_raw);

    const int t  = threadIdx.x;
    const int b0 = blockIdx.x * MB;

    // ---------------- stage resident weights & init state ----------------
    for (int e = t; e < Hh * Dd; e += NT) sm.hist[e] = histW[e];
    for (int e = t; e < Dd * Dd; e += NT) {
        int k = e >> 6, jj = e & 63;
        sm.tdxT[e] = tdxW[jj * Dd + k];
        sm.frT[e]  = frW[jj * Dd + k];
    }
    for (int e = t; e < 2 * Dd * Dd; e += NT) sm.wc[e] = wcW[e];
    for (int e = t; e < Hh; e += NT) sm.tdh_b[e] = tdhB[e];
    if (t < Dd) {
        sm.tdx_b[t] = tdxB[t]; sm.hist_b[t] = histB[t];
        sm.fr_b[t]  = frB[t];  sm.wc_b[t]   = wcB[t];
    }
    for (int e = t; e < 4 * Hh; e += NT) sm.lstm_b[e] = lstmB[e];
    for (int e = t; e < MB * Hh; e += NT) sm.cs[e] = 0.f;
    for (int e = t; e < 4 * 2 * Hh; e += NT) sm.hp[e] = 0.f;

    // step-0 inputs: 512 threads load exactly one element each
    {
        int r = t >> 6, jj = t & 63;
        int off = ((b0 + r) * Tt + 0) * Dd + jj;
        float xv = values[off], mv = masks[off], dv = deltas[off];
        sm.xs[t] = xv; sm.ms[t] = mv;
        sm.mp[(r >> 1) * 128 + jj * 2 + (r & 1)] = mv;
        sm.dp[(r >> 1) * 128 + jj * 2 + (r & 1)] = dv;
    }
    __syncthreads();

    float pf_x[2], pf_m[2], pf_d[2];   // prefetch registers (wg1)

    for (int step = 0; step < Tt; ++step) {
        // ============ S1: [wg0] gamma_h + h decay ∥ [wg1] gamma_x -> alpha
        if (t < 256) {
            const int c = t;
            u64 a[4];
            #pragma unroll
            for (int p = 0; p < 4; p++) a[p] = 0ULL;
            #pragma unroll 4
            for (int k = 0; k < Dd; k++) {
                u64 wd = dup2(tdhT_g[k * Hh + c]);
                #pragma unroll
                for (int p = 0; p < 4; p++) {
                    u64 d2 = *(const u64*)(sm.dp + p * 128 + k * 2);
                    a[p] = fma2(d2, wd, a[p]);
                }
            }
            float bb = sm.tdh_b[c];
            #pragma unroll
            for (int p = 0; p < 4; p++) {
                float a0, a1; upk2(a[p], a0, a1);
                float g0 = __expf(-fmaxf(a0 + bb, 0.f));
                float g1 = __expf(-fmaxf(a1 + bb, 0.f));
                float2 hv = *(float2*)(sm.hp + p * 512 + c * 2);
                hv.x *= g0; hv.y *= g1;
                *(float2*)(sm.hp + p * 512 + c * 2) = hv;
            }
        } else {
            const int u = t - 256;
            const int j = u & 63, rp = u >> 6;
            // gamma_x (paired rows)
            u64 g = dup2(sm.tdx_b[j]);
            #pragma unroll 4
            for (int k = 0; k < Dd; k++) {
                u64 wd = dup2(sm.tdxT[k * Dd + j]);
                u64 d2 = *(const u64*)(sm.dp + rp * 128 + k * 2);
                g = fma2(d2, wd, g);
            }
            float g0, g1; upk2(g, g0, g1);
            g0 = __expf(-fmaxf(g0, 0.f));
            g1 = __expf(-fmaxf(g1, 0.f));
            *(float2*)(sm.gxp + rp * 128 + j * 2) = make_float2(g0, g1);
            asm volatile("bar.sync 1, 256;" ::: "memory");
            // alpha = [gamma_x, m] @ wc + b   (gxp/mp with j role -> k)
            u64 al = dup2(sm.wc_b[j]);
            #pragma unroll 4
            for (int k = 0; k < Dd; k++) {
                u64 wa = dup2(sm.wc[k * Dd + j]);
                u64 wb = dup2(sm.wc[(Dd + k) * Dd + j]);
                u64 g2 = *(const u64*)(sm.gxp + rp * 128 + k * 2);
                u64 m2 = *(const u64*)(sm.mp  + rp * 128 + k * 2);
                al = fma2(g2, wa, al);
                al = fma2(m2, wb, al);
            }
            float a0, a1; upk2(al, a0, a1);
            *(float2*)(sm.alp + rp * 128 + j * 2) = make_float2(a0, a1);
        }
        __syncthreads();

        // ============ C: x_h = h @ hist_W (k-split 8-way), partials in zp ===
        float2* cpart = (float2*)sm.zp;    // [kq*4+p][j]
        {
            const int j = t & 63, kq = t >> 6;
            u64 a[4];
            #pragma unroll
            for (int p = 0; p < 4; p++) a[p] = 0ULL;
            const int k0 = kq * 32;
            #pragma unroll 4
            for (int kk = 0; kk < 32; kk++) {
                int k = k0 + kk;
                u64 wd = dup2(sm.hist[k * Dd + j]);
                #pragma unroll
                for (int p = 0; p < 4; p++) {
                    u64 h2 = *(const u64*)(sm.hp + p * 512 + k * 2);
                    a[p] = fma2(h2, wd, a[p]);
                }
            }
            #pragma unroll
            for (int p = 0; p < 4; p++) {
                float a0, a1; upk2(a[p], a0, a1);
                cpart[(kq * 4 + p) * 64 + j] = make_float2(a0, a1);
            }
        }
        __syncthreads();
        // reduce partials -> x_h, x_c (each thread one (row, col))
        {
            const int j = t & 63, p = (t >> 6) & 3, par = t >> 8;
            const float* cp = (const float*)cpart;
            float s = 0.f;
            #pragma unroll
            for (int kq = 0; kq < 8; kq++)
                s += cp[((kq * 4 + p) * 64 + j) * 2 + par];
            float xh = s + sm.hist_b[j];
            int r = 2 * p + par;
            float m = sm.ms[r * Dd + j], x = sm.xs[r * Dd + j];
            float xc = m * x + (1.f - m) * xh;
            sm.xcp[p * 128 + j * 2 + par] = xc;
            sm.xhp[p * 128 + j * 2 + par] = xh;
        }
        __syncthreads();

        // ============ D: [wg0] z_h -> c_h -> c_c (+imputation out)
        //              [wg1] prefetch next step inputs ======================
        if (t < 256) {
            const int j = t & 63, rp = t >> 6;
            u64 z = dup2(sm.fr_b[j]);
            #pragma unroll 4
            for (int k = 0; k < Dd; k++) {
                u64 wf = dup2(sm.frT[k * Dd + j]);
                u64 x2 = *(const u64*)(sm.xcp + rp * 128 + k * 2);
                z = fma2(x2, wf, z);
            }
            float z0, z1; upk2(z, z0, z1);
            float2 al = *(const float2*)(sm.alp + rp * 128 + j * 2);
            float2 xh = *(const float2*)(sm.xhp + rp * 128 + j * 2);
            int r0 = 2 * rp, r1 = r0 + 1;
            float m0 = sm.ms[r0 * Dd + j], m1 = sm.ms[r1 * Dd + j];
            float x0 = sm.xs[r0 * Dd + j], x1 = sm.xs[r1 * Dd + j];
            float ch0 = al.x * z0 + (1.f - al.x) * xh.x;
            float ch1 = al.y * z1 + (1.f - al.y) * xh.y;
            float cc0 = m0 * x0 + (1.f - m0) * ch0;
            float cc1 = m1 * x1 + (1.f - m1) * ch1;
            *(float2*)(sm.ccp + rp * 128 + j * 2) = make_float2(cc0, cc1);
            impout[((b0 + r0) * Tt + step) * Dd + j] = cc0;
            impout[((b0 + r1) * Tt + step) * Dd + j] = cc1;
        } else if (step + 1 < Tt) {
            const int u = t - 256;
            #pragma unroll
            for (int s = 0; s < 2; s++) {
                int e = u + s * 256;
                int r = e >> 6, jj = e & 63;
                int off = ((b0 + r) * Tt + (step + 1)) * Dd + jj;
                pf_x[s] = values[off]; pf_m[s] = masks[off]; pf_d[s] = deltas[off];
            }
        }
        __syncthreads();

        // ============ E: z = [c_c,m]@lstm_k + h@lstm_rk + b; activations ====
        {
            u64 acc[4][2];
            float bq0 = sm.lstm_b[2 * t], bq1 = sm.lstm_b[2 * t + 1];
            #pragma unroll
            for (int p = 0; p < 4; p++) { acc[p][0] = dup2(bq0); acc[p][1] = dup2(bq1); }

            const float2* rk2 = (const float2*)lstmRK;
            #pragma unroll 2
            for (int k = 0; k < Hh; k += 2) {
                float2 w0 = rk2[k * 512 + t];
                float2 w1 = rk2[(k + 1) * 512 + t];
                u64 wa0 = dup2(w0.x), wb0 = dup2(w0.y);
                u64 wa1 = dup2(w1.x), wb1 = dup2(w1.y);
                #pragma unroll
                for (int p = 0; p < 4; p++) {
                    float4 hv = *(const float4*)(sm.hp + p * 512 + k * 2);
                    u64 h0 = ((const u64*)&hv)[0];
                    u64 h1 = ((const u64*)&hv)[1];
                    acc[p][0] = fma2(h0, wa0, acc[p][0]);
                    acc[p][1] = fma2(h0, wb0, acc[p][1]);
                    acc[p][0] = fma2(h1, wa1, acc[p][0]);
                    acc[p][1] = fma2(h1, wb1, acc[p][1]);
                }
            }
            const float2* kk2 = (const float2*)lstmK;
            #pragma unroll 2
            for (int k = 0; k < Dd; k += 2) {
                float2 w0 = kk2[k * 512 + t];
                float2 w1 = kk2[(k + 1) * 512 + t];
                u64 wa0 = dup2(w0.x), wb0 = dup2(w0.y);
                u64 wa1 = dup2(w1.x), wb1 = dup2(w1.y);
                #pragma unroll
                for (int p = 0; p < 4; p++) {
                    float4 cv = *(const float4*)(sm.ccp + p * 128 + k * 2);
                    u64 c0 = ((const u64*)&cv)[0];
                    u64 c1 = ((const u64*)&cv)[1];
                    acc[p][0] = fma2(c0, wa0, acc[p][0]);
                    acc[p][1] = fma2(c0, wb0, acc[p][1]);
                    acc[p][0] = fma2(c1, wa1, acc[p][0]);
                    acc[p][1] = fma2(c1, wb1, acc[p][1]);
                }
            }
            #pragma unroll 2
            for (int k = 0; k < Dd; k += 2) {
                float2 w0 = kk2[(Dd + k) * 512 + t];
                float2 w1 = kk2[(Dd + k + 1) * 512 + t];
                u64 wa0 = dup2(w0.x), wb0 = dup2(w0.y);
                u64 wa1 = dup2(w1.x), wb1 = dup2(w1.y);
                #pragma unroll
                for (int p = 0; p < 4; p++) {
                    float4 mv = *(const float4*)(sm.mp + p * 128 + k * 2);
                    u64 m0 = ((const u64*)&mv)[0];
                    u64 m1 = ((const u64*)&mv)[1];
                    acc[p][0] = fma2(m0, wa0, acc[p][0]);
                    acc[p][1] = fma2(m0, wb0, acc[p][1]);
                    acc[p][0] = fma2(m1, wa1, acc[p][0]);
                    acc[p][1] = fma2(m1, wb1, acc[p][1]);
                }
            }
            const int gate = t >> 7;   // cols 2t,2t+1 share a gate
            #pragma unroll
            for (int p = 0; p < 4; p++) {
                #pragma unroll
                for (int q = 0; q < 2; q++) {
                    float v0, v1; upk2(acc[p][q], v0, v1);
                    float a0, a1;
                    if (gate == 2) { a0 = tanhfast(v0); a1 = tanhfast(v1); }
                    else           { a0 = sigf(v0);     a1 = sigf(v1);     }
                    int col = 2 * t + q;
                    *(float2*)(sm.zp + p * 2048 + col * 2) = make_float2(a0, a1);
                }
            }
        }
        __syncthreads();

        // ============ F: [wg0] c,h update  [wg1] store prefetched inputs ====
        if (t < 256) {
            int r = t >> 5;
            int p = r >> 1, par = r & 1;
            int c0 = (t & 31) * 8;
            #pragma unroll
            for (int cc = 0; cc < 8; cc++) {
                int c = c0 + cc;
                float iv = sm.zp[p * 2048 + (0 * Hh + c) * 2 + par];
                float fv = sm.zp[p * 2048 + (1 * Hh + c) * 2 + par];
                float gv = sm.zp[p * 2048 + (2 * Hh + c) * 2 + par];
                float ov = sm.zp[p * 2048 + (3 * Hh + c) * 2 + par];
                float cold = sm.cs[r * Hh + c];
                float cnew = fv * cold + iv * gv;
                sm.cs[r * Hh + c] = cnew;
                sm.hp[p * 512 + c * 2 + par] = ov * tanhfast(cnew);
            }
        } else if (step + 1 < Tt) {
            const int u = t - 256;
            #pragma unroll
            for (int s = 0; s < 2; s++) {
                int e = u + s * 256;
                int r = e >> 6, jj = e & 63;
                sm.xs[e] = pf_x[s]; sm.ms[e] = pf_m[s];
                sm.mp[(r >> 1) * 128 + jj * 2 + (r & 1)] = pf_m[s];
                sm.dp[(r >> 1) * 128 + jj * 2 + (r & 1)] = pf_d[s];
            }
        }
        __syncthreads();
    }

    // ---------------- final: y = h @ out_W + out_b ----------------
    {
        int w = t >> 5, lane = t & 31;
        if (w < MB) {
            float s = 0.f;
            for (int k = lane; k < Hh; k += 32)
                s += sm.hp[(w >> 1) * 512 + k * 2 + (w & 1)] * outW[k];
            #pragma unroll
            for (int o = 16; o > 0; o >>= 1)
                s += __shfl_down_sync(0xffffffffu, s, o);
            if (lane == 0) yout[b0 + w] = s + outB[0];
        }
    }
}

extern "C" void kernel_launch(void* const* d_in, const int* in_sizes, int n_in,
                              void* d_out, int out_size) {
    const float* values = (const float*)d_in[0];
    const float* masks  = (const float*)d_in[1];
    const float* deltas = (const float*)d_in[2];
    const float* tdhW   = (const float*)d_in[3];
    const float* tdhB   = (const float*)d_in[4];
    const float* tdxW   = (const float*)d_in[5];
    const float* tdxB   = (const float*)d_in[6];
    const float* histW  = (const float*)d_in[7];
    const float* histB  = (const float*)d_in[8];
    const float* frW    = (const float*)d_in[9];
    const float* frB    = (const float*)d_in[10];
    const float* wcW    = (const float*)d_in[11];
    const float* wcB    = (const float*)d_in[12];
    const float* lstmK  = (const float*)d_in[13];
    const float* lstmRK = (const float*)d_in[14];
    const float* lstmB  = (const float*)d_in[15];
    const float* outW   = (const float*)d_in[16];
    const float* outB   = (const float*)d_in[17];

    float* yout   = (float*)d_out;       // y_h [B,1] first
    float* impout = yout + Bsz;          // imputations [B,T,D]

    transpose_tdh_kernel<<<64, 256>>>(tdhW);

    cudaFuncSetAttribute(rits_kernel, cudaFuncAttributeMaxDynamicSharedMemorySize,
                         (int)sizeof(Smem));
    rits_kernel<<<GRID, NT, sizeof(Smem)>>>(
        values, masks, deltas, tdhB, tdxW, tdxB, histW, histB,
        frW, frB, wcW, wcB, lstmK, lstmRK, lstmB, outW, outB, yout, impout);
}

// round 4
// speedup vs baseline: 1.2871x; 1.2871x over previous
#include <cuda_runtime.h>
#include <cstdint>

#define Bsz 1024
#define Tt  128
#define Dd  64
#define Hh  256
#define MB  8
#define NT  512
#define GRID 128

typedef unsigned long long u64;

// ------------------- device scratch (precomputed, per call) -------------------
__device__ float tdhT_g[Dd * Hh];                    // td_h_W^T  [k][c]
__device__ float tdxT_g[Dd * Dd];                    // td_x_W^T  [k][j]
__device__ float Gh_g[Bsz * Tt * Hh];                // gamma_h   [b*T+t][256]
__device__ float alpha_g[Bsz * Tt * Dd];             // alpha     [b*T+t][64]
__device__ float zprep_g[(Bsz / 2) * Tt * 1024 * 2]; // lstm_b + m@Wm, paired (b even, b odd)

__device__ __forceinline__ u64 dup2(float w) {
    u64 r; asm("mov.b64 %0, {%1,%1};" : "=l"(r) : "f"(w)); return r;
}
__device__ __forceinline__ void upk2(u64 v, float& lo, float& hi) {
    asm("mov.b64 {%0,%1}, %2;" : "=f"(lo), "=f"(hi) : "l"(v));
}
__device__ __forceinline__ u64 fma2(u64 a, u64 b, u64 c) {
    u64 d; asm("fma.rn.f32x2 %0, %1, %2, %3;" : "=l"(d) : "l"(a), "l"(b), "l"(c)); return d;
}
__device__ __forceinline__ u64 add2(u64 a, u64 b) {
    u64 d; asm("add.rn.f32x2 %0, %1, %2;" : "=l"(d) : "l"(a), "l"(b)); return d;
}
__device__ __forceinline__ float sigf(float x) {
    return __fdividef(1.f, 1.f + __expf(-x));
}
__device__ __forceinline__ float tanhfast(float x) {
    return __fdividef(2.f, 1.f + __expf(-2.f * x)) - 1.f;
}

// ============================ precompute kernels ============================

__global__ void transpose_kernel(const float* __restrict__ tdhW,
                                 const float* __restrict__ tdxW) {
    int idx = blockIdx.x * 256 + threadIdx.x;
    if (idx < Hh * Dd) {                       // tdhW (256,64) -> [k][c]
        int c = idx >> 6, k = idx & 63;
        tdhT_g[k * Hh + c] = tdhW[idx];
    } else if (idx < Hh * Dd + Dd * Dd) {      // tdxW (64,64) -> [k][j]
        int e = idx - Hh * Dd;
        int j = e >> 6, k = e & 63;
        tdxT_g[k * Dd + j] = tdxW[e];
    }
}

// gamma_h = exp(-relu(d @ td_h_W^T + b)) for all (b,t). 8 rows/CTA.
__global__ void __launch_bounds__(256) pre_gh_kernel(
    const float* __restrict__ deltas, const float* __restrict__ tdhB)
{
    __shared__ float dp[4 * Dd * 2];   // paired rows
    const int tid = threadIdx.x;
    const int row0 = blockIdx.x * 8;
    for (int e = tid; e < 8 * Dd; e += 256) {
        int r = e >> 6, k = e & 63;
        dp[(r >> 1) * 128 + k * 2 + (r & 1)] = deltas[(row0 + r) * Dd + k];
    }
    __syncthreads();
    const int c = tid;
    u64 a[4];
    #pragma unroll
    for (int p = 0; p < 4; p++) a[p] = 0ULL;
    #pragma unroll 4
    for (int k = 0; k < Dd; k++) {
        u64 wd = dup2(tdhT_g[k * Hh + c]);
        #pragma unroll
        for (int p = 0; p < 4; p++)
            a[p] = fma2(*(const u64*)(dp + p * 128 + k * 2), wd, a[p]);
    }
    float bb = tdhB[c];
    #pragma unroll
    for (int p = 0; p < 4; p++) {
        float a0, a1; upk2(a[p], a0, a1);
        Gh_g[(row0 + 2 * p)     * Hh + c] = __expf(-fmaxf(a0 + bb, 0.f));
        Gh_g[(row0 + 2 * p + 1) * Hh + c] = __expf(-fmaxf(a1 + bb, 0.f));
    }
}

// gamma_x then alpha for all (b,t). 8 rows/CTA.
__global__ void __launch_bounds__(256) pre_alpha_kernel(
    const float* __restrict__ deltas, const float* __restrict__ masks,
    const float* __restrict__ tdxB,
    const float* __restrict__ wcW, const float* __restrict__ wcB)
{
    __shared__ float dp[4 * Dd * 2], mp[4 * Dd * 2], gxp[4 * Dd * 2];
    const int tid = threadIdx.x;
    const int row0 = blockIdx.x * 8;
    for (int e = tid; e < 8 * Dd; e += 256) {
        int r = e >> 6, k = e & 63;
        dp[(r >> 1) * 128 + k * 2 + (r & 1)] = deltas[(row0 + r) * Dd + k];
        mp[(r >> 1) * 128 + k * 2 + (r & 1)] = masks[(row0 + r) * Dd + k];
    }
    __syncthreads();
    const int j = tid & 63, pg = tid >> 6;
    u64 g = dup2(tdxB[j]);
    #pragma unroll 4
    for (int k = 0; k < Dd; k++)
        g = fma2(*(const u64*)(dp + pg * 128 + k * 2), dup2(tdxT_g[k * Dd + j]), g);
    float g0, g1; upk2(g, g0, g1);
    gxp[pg * 128 + j * 2 + 0] = __expf(-fmaxf(g0, 0.f));
    gxp[pg * 128 + j * 2 + 1] = __expf(-fmaxf(g1, 0.f));
    __syncthreads();
    u64 al = dup2(wcB[j]);
    #pragma unroll 4
    for (int k = 0; k < Dd; k++) {
        al = fma2(*(const u64*)(gxp + pg * 128 + k * 2), dup2(wcW[k * Dd + j]), al);
        al = fma2(*(const u64*)(mp  + pg * 128 + k * 2), dup2(wcW[(Dd + k) * Dd + j]), al);
    }
    float a0, a1; upk2(al, a0, a1);
    alpha_g[(row0 + 2 * pg)     * Dd + j] = a0;
    alpha_g[(row0 + 2 * pg + 1) * Dd + j] = a1;
}

// zpre = lstm_b + m @ lstm_k[64:128], stored pair-interleaved by (b even, b odd).
// grid (4 col-tiles, 8 t-blocks, 512 b-pairs), NT=256, dyn smem 76KB.
__global__ void __launch_bounds__(256) pre_z_kernel(
    const float* __restrict__ masks, const float* __restrict__ lstmK,
    const float* __restrict__ lstmB)
{
    extern __shared__ float psm[];
    float* W  = psm;               // [64][256]
    float* mp = W + 64 * 256;      // [16 t][64 k][2 par]
    float* lb = mp + 16 * 128;     // [256]
    const int tid = threadIdx.x;
    const int c0 = blockIdx.x * 256;
    const int t0 = blockIdx.y * 16;
    const int bp = blockIdx.z;

    for (int e = tid; e < 64 * 256; e += 256) {
        int k = e >> 8, c = e & 255;
        W[e] = lstmK[(Dd + k) * 1024 + c0 + c];
    }
    if (tid < 256) lb[tid] = lstmB[c0 + tid];
    #pragma unroll
    for (int par = 0; par < 2; par++)
        for (int e = tid; e < 16 * 64; e += 256) {
            int tt = e >> 6, k = e & 63;
            mp[tt * 128 + k * 2 + par] = masks[((2 * bp + par) * Tt + t0 + tt) * Dd + k];
        }
    __syncthreads();

    const int cq = tid & 63;   // 4 cols: c0 + cq*4 ..
    const int pg = tid >> 6;   // 4 t's:  t0 + pg*4 ..
    u64 acc[4][4];
    #pragma unroll
    for (int tt = 0; tt < 4; tt++)
        #pragma unroll
        for (int c = 0; c < 4; c++) acc[tt][c] = 0ULL;

    #pragma unroll 2
    for (int k = 0; k < Dd; k++) {
        float4 w = *(const float4*)(W + k * 256 + cq * 4);
        u64 w0 = dup2(w.x), w1 = dup2(w.y), w2 = dup2(w.z), w3 = dup2(w.w);
        #pragma unroll
        for (int tt = 0; tt < 4; tt++) {
            u64 m2 = *(const u64*)(mp + (pg * 4 + tt) * 128 + k * 2);
            acc[tt][0] = fma2(m2, w0, acc[tt][0]);
            acc[tt][1] = fma2(m2, w1, acc[tt][1]);
            acc[tt][2] = fma2(m2, w2, acc[tt][2]);
            acc[tt][3] = fma2(m2, w3, acc[tt][3]);
        }
    }
    float4 lbv = *(const float4*)(lb + cq * 4);
    u64 lb0 = dup2(lbv.x), lb1 = dup2(lbv.y), lb2 = dup2(lbv.z), lb3 = dup2(lbv.w);
    #pragma unroll
    for (int tt = 0; tt < 4; tt++) {
        int tg = t0 + pg * 4 + tt;
        int col = c0 + cq * 4;
        u64* dst = (u64*)(zprep_g + ((size_t)(bp * Tt + tg) * 1024 + col) * 2);
        dst[0] = add2(acc[tt][0], lb0);
        dst[1] = add2(acc[tt][1], lb1);
        dst[2] = add2(acc[tt][2], lb2);
        dst[3] = add2(acc[tt][3], lb3);
    }
}

// ============================ main recurrent kernel ============================

struct __align__(16) Smem {
    float hist[Hh * Dd];      // 64 KB
    float frT[Dd * Dd];       // 16 KB
    float hp[4 * 2 * Hh];     //  8 KB  h paired [p][k*2+par]
    float cs[MB * Hh];        //  8 KB
    float zp[4 * 2 * 4 * Hh]; // 32 KB  gate acts (alias: x_h partials)
    float gh[MB * Hh];        //  8 KB  G_h[t+1] staging
    float xs[MB * Dd], ms[MB * Dd];
    float alp[4 * 2 * Dd];
    float xcp[4 * 2 * Dd], xhp[4 * 2 * Dd], ccp[4 * 2 * Dd];
    float hist_b[Dd], fr_b[Dd];
};

template <int STRIDE>
__device__ __forceinline__ void eblk(const float* src, int k0,
                                     float2 w0, float2 w1, u64 (&acc)[4][2]) {
    u64 wa0 = dup2(w0.x), wb0 = dup2(w0.y);
    u64 wa1 = dup2(w1.x), wb1 = dup2(w1.y);
    #pragma unroll
    for (int p = 0; p < 4; p++) {
        float4 hv = *(const float4*)(src + p * STRIDE + k0 * 2);
        u64 h0 = ((const u64*)&hv)[0];
        u64 h1 = ((const u64*)&hv)[1];
        acc[p][0] = fma2(h0, wa0, acc[p][0]);
        acc[p][1] = fma2(h0, wb0, acc[p][1]);
        acc[p][0] = fma2(h1, wa1, acc[p][0]);
        acc[p][1] = fma2(h1, wb1, acc[p][1]);
    }
}

__global__ void __launch_bounds__(NT, 1) rits_kernel(
    const float* __restrict__ values, const float* __restrict__ masks,
    const float* __restrict__ histW, const float* __restrict__ histB,
    const float* __restrict__ frW, const float* __restrict__ frB,
    const float* __restrict__ lstmK, const float* __restrict__ lstmRK,
    const float* __restrict__ outW, const float* __restrict__ outB,
    float* __restrict__ yout, float* __restrict__ impout)
{
    extern __shared__ char smem_raw[];
    Smem& sm = *reinterpret_cast<Smem*>(smem_raw);

    const int t  = threadIdx.x;
    const int b0 = blockIdx.x * MB;

    // ---- stage resident weights & init state ----
    for (int e = t; e < Hh * Dd; e += NT) sm.hist[e] = histW[e];
    for (int e = t; e < Dd * Dd; e += NT) {
        int k = e >> 6, jj = e & 63;
        sm.frT[e] = frW[jj * Dd + k];
    }
    if (t < Dd) { sm.hist_b[t] = histB[t]; sm.fr_b[t] = frB[t]; }
    for (int e = t; e < MB * Hh; e += NT) sm.cs[e] = 0.f;
    for (int e = t; e < 4 * 2 * Hh; e += NT) sm.hp[e] = 0.f;
    {   // step-0 inputs + alpha[0]
        int r = t >> 6, jj = t & 63;
        int off = ((b0 + r) * Tt + 0) * Dd + jj;
        sm.xs[t] = values[off]; sm.ms[t] = masks[off];
        int j = t & 63, p = (t >> 6) & 3, par = t >> 8;
        sm.alp[p * 128 + j * 2 + par] = alpha_g[((b0 + 2 * p + par) * Tt + 0) * Dd + j];
    }
    __syncthreads();

    float pf_x[2], pf_m[2], pf_a0, pf_a1;   // wg1 prefetch regs

    for (int step = 0; step < Tt; ++step) {
        // ---- P1 (all): x_h partials, k-split 8-way, into zp alias ----
        float2* cpart = (float2*)sm.zp;
        {
            const int j = t & 63, kq = t >> 6;
            u64 a[4];
            #pragma unroll
            for (int p = 0; p < 4; p++) a[p] = 0ULL;
            const int k0 = kq * 32;
            #pragma unroll 4
            for (int kk = 0; kk < 32; kk++) {
                int k = k0 + kk;
                u64 wd = dup2(sm.hist[k * Dd + j]);
                #pragma unroll
                for (int p = 0; p < 4; p++)
                    a[p] = fma2(*(const u64*)(sm.hp + p * 512 + k * 2), wd, a[p]);
            }
            #pragma unroll
            for (int p = 0; p < 4; p++) {
                float a0, a1; upk2(a[p], a0, a1);
                cpart[(kq * 4 + p) * 64 + j] = make_float2(a0, a1);
            }
        }
        __syncthreads();

        // ---- P3: wg0 {reduce -> x_c; z_h -> c_c -> impout} | wg1 {prefetch} --
        if (t < 256) {
            const int j = t & 63, p = t >> 6;
            const float* cp = (const float*)cpart;
            float xh[2], xc[2];
            #pragma unroll
            for (int par = 0; par < 2; par++) {
                float s = 0.f;
                #pragma unroll
                for (int kq = 0; kq < 8; kq++)
                    s += cp[((kq * 4 + p) * 64 + j) * 2 + par];
                xh[par] = s + sm.hist_b[j];
                int r = 2 * p + par;
                float m = sm.ms[r * Dd + j], x = sm.xs[r * Dd + j];
                xc[par] = m * x + (1.f - m) * xh[par];
                sm.xcp[p * 128 + j * 2 + par] = xc[par];
                sm.xhp[p * 128 + j * 2 + par] = xh[par];
            }
            asm volatile("bar.sync 1, 256;" ::: "memory");
            // z_h, alpha-combine, imputation
            u64 z = dup2(sm.fr_b[j]);
            #pragma unroll 4
            for (int k = 0; k < Dd; k++)
                z = fma2(*(const u64*)(sm.xcp + p * 128 + k * 2),
                         dup2(sm.frT[k * Dd + j]), z);
            float z0, z1; upk2(z, z0, z1);
            float2 al = *(const float2*)(sm.alp + p * 128 + j * 2);
            int r0 = 2 * p, r1 = r0 + 1;
            float m0 = sm.ms[r0 * Dd + j], m1 = sm.ms[r1 * Dd + j];
            float x0 = sm.xs[r0 * Dd + j], x1 = sm.xs[r1 * Dd + j];
            float ch0 = al.x * z0 + (1.f - al.x) * xh[0];
            float ch1 = al.y * z1 + (1.f - al.y) * xh[1];
            float cc0 = m0 * x0 + (1.f - m0) * ch0;
            float cc1 = m1 * x1 + (1.f - m1) * ch1;
            *(float2*)(sm.ccp + p * 128 + j * 2) = make_float2(cc0, cc1);
            impout[(r0 + b0) * Tt * Dd + step * Dd + j] = cc0;
            impout[(r1 + b0) * Tt * Dd + step * Dd + j] = cc1;
        } else if (step + 1 < Tt) {
            const int u = t - 256;
            #pragma unroll
            for (int s = 0; s < 2; s++) {
                int e = u + s * 256;
                int r = e >> 6, jj = e & 63;
                int off = ((b0 + r) * Tt + (step + 1)) * Dd + jj;
                pf_x[s] = values[off]; pf_m[s] = masks[off];
            }
            {
                int j = u & 63, rp = u >> 6;
                pf_a0 = alpha_g[((b0 + 2 * rp)     * Tt + step + 1) * Dd + j];
                pf_a1 = alpha_g[((b0 + 2 * rp + 1) * Tt + step + 1) * Dd + j];
            }
            {
                int r = u >> 5, c0 = (u & 31) * 8;
                const float* gsrc = Gh_g + ((b0 + r) * Tt + (step + 1)) * Hh + c0;
                float4 g0 = *(const float4*)gsrc;
                float4 g1 = *(const float4*)(gsrc + 4);
                *(float4*)(sm.gh + r * Hh + c0)     = g0;
                *(float4*)(sm.gh + r * Hh + c0 + 4) = g1;
            }
        }
        __syncthreads();

        // ---- P4 (all): z = zpre + c_c@Wk_cc + h@Wrk ; activations ----
        {
            // issue zpre loads up front, consume at the end
            u64 zin[4][2];
            const float4* zp4 = (const float4*)zprep_g;
            #pragma unroll
            for (int p = 0; p < 4; p++) {
                float4 v = zp4[((size_t)(b0 / 2 + p) * Tt + step) * 512 + t];
                zin[p][0] = ((const u64*)&v)[0];
                zin[p][1] = ((const u64*)&v)[1];
            }
            u64 acc[4][2];
            #pragma unroll
            for (int p = 0; p < 4; p++) { acc[p][0] = 0ULL; acc[p][1] = 0ULL; }

            // recurrent part, k = 0..255, 4k-deep weight pipeline
            const float2* rk2 = (const float2*)lstmRK;
            float2 wA0 = rk2[t], wA1 = rk2[512 + t];
            float2 wB0 = rk2[1024 + t], wB1 = rk2[1536 + t];
            #pragma unroll 2
            for (int k = 0; k < Hh; k += 4) {
                int kn = (k + 4) & 255;
                float2 nA0 = rk2[kn * 512 + t],       nA1 = rk2[(kn + 1) * 512 + t];
                float2 nB0 = rk2[(kn + 2) * 512 + t], nB1 = rk2[(kn + 3) * 512 + t];
                eblk<512>(sm.hp, k,     wA0, wA1, acc);
                eblk<512>(sm.hp, k + 2, wB0, wB1, acc);
                wA0 = nA0; wA1 = nA1; wB0 = nB0; wB1 = nB1;
            }
            // c_c part, k = 0..63
            const float2* kk2 = (const float2*)lstmK;
            wA0 = kk2[t]; wA1 = kk2[512 + t];
            wB0 = kk2[1024 + t]; wB1 = kk2[1536 + t];
            #pragma unroll 2
            for (int k = 0; k < Dd; k += 4) {
                int kn = (k + 4) & 63;
                float2 nA0 = kk2[kn * 512 + t],       nA1 = kk2[(kn + 1) * 512 + t];
                float2 nB0 = kk2[(kn + 2) * 512 + t], nB1 = kk2[(kn + 3) * 512 + t];
                eblk<128>(sm.ccp, k,     wA0, wA1, acc);
                eblk<128>(sm.ccp, k + 2, wB0, wB1, acc);
                wA0 = nA0; wA1 = nA1; wB0 = nB0; wB1 = nB1;
            }
            const int gate = t >> 7;
            #pragma unroll
            for (int p = 0; p < 4; p++) {
                #pragma unroll
                for (int q = 0; q < 2; q++) {
                    u64 zv = add2(acc[p][q], zin[p][q]);
                    float v0, v1; upk2(zv, v0, v1);
                    float a0, a1;
                    if (gate == 2) { a0 = tanhfast(v0); a1 = tanhfast(v1); }
                    else           { a0 = sigf(v0);     a1 = sigf(v1);     }
                    int col = 2 * t + q;
                    *(float2*)(sm.zp + p * 2048 + col * 2) = make_float2(a0, a1);
                }
            }
        }
        __syncthreads();

        // ---- P5: wg0 {c,h update (+ fused next-step decay)} | wg1 {commit} --
        if (t < 256) {
            int r = t >> 5;
            int p = r >> 1, par = r & 1;
            int c0 = (t & 31) * 8;
            bool last = (step == Tt - 1);
            float4 gA = *(const float4*)(sm.gh + r * Hh + c0);
            float4 gB = *(const float4*)(sm.gh + r * Hh + c0 + 4);
            float gv8[8] = {gA.x, gA.y, gA.z, gA.w, gB.x, gB.y, gB.z, gB.w};
            #pragma unroll
            for (int cc = 0; cc < 8; cc++) {
                int c = c0 + cc;
                float iv = sm.zp[p * 2048 + (0 * Hh + c) * 2 + par];
                float fv = sm.zp[p * 2048 + (1 * Hh + c) * 2 + par];
                float gg = sm.zp[p * 2048 + (2 * Hh + c) * 2 + par];
                float ov = sm.zp[p * 2048 + (3 * Hh + c) * 2 + par];
                float cold = sm.cs[r * Hh + c];
                float cnew = fv * cold + iv * gg;
                sm.cs[r * Hh + c] = cnew;
                float hh = ov * tanhfast(cnew);
                if (!last) hh *= gv8[cc];
                sm.hp[p * 512 + c * 2 + par] = hh;
            }
        } else if (step + 1 < Tt) {
            const int u = t - 256;
            #pragma unroll
            for (int s = 0; s < 2; s++) {
                int e = u + s * 256;
                sm.xs[e] = pf_x[s]; sm.ms[e] = pf_m[s];
            }
            int j = u & 63, rp = u >> 6;
            *(float2*)(sm.alp + rp * 128 + j * 2) = make_float2(pf_a0, pf_a1);
        }
        __syncthreads();
    }

    // ---- final: y = h @ out_W + out_b ----
    {
        int w = t >> 5, lane = t & 31;
        if (w < MB) {
            float s = 0.f;
            for (int k = lane; k < Hh; k += 32)
                s += sm.hp[(w >> 1) * 512 + k * 2 + (w & 1)] * outW[k];
            #pragma unroll
            for (int o = 16; o > 0; o >>= 1)
                s += __shfl_down_sync(0xffffffffu, s, o);
            if (lane == 0) yout[b0 + w] = s + outB[0];
        }
    }
}

// ================================ launcher ================================

extern "C" void kernel_launch(void* const* d_in, const int* in_sizes, int n_in,
                              void* d_out, int out_size) {
    const float* values = (const float*)d_in[0];
    const float* masks  = (const float*)d_in[1];
    const float* deltas = (const float*)d_in[2];
    const float* tdhW   = (const float*)d_in[3];
    const float* tdhB   = (const float*)d_in[4];
    const float* tdxW   = (const float*)d_in[5];
    const float* tdxB   = (const float*)d_in[6];
    const float* histW  = (const float*)d_in[7];
    const float* histB  = (const float*)d_in[8];
    const float* frW    = (const float*)d_in[9];
    const float* frB    = (const float*)d_in[10];
    const float* wcW    = (const float*)d_in[11];
    const float* wcB    = (const float*)d_in[12];
    const float* lstmK  = (const float*)d_in[13];
    const float* lstmRK = (const float*)d_in[14];
    const float* lstmB  = (const float*)d_in[15];
    const float* outW   = (const float*)d_in[16];
    const float* outB   = (const float*)d_in[17];

    float* yout   = (float*)d_out;       // y_h [B,1] first
    float* impout = yout + Bsz;          // imputations [B,T,D]

    transpose_kernel<<<(Hh * Dd + Dd * Dd + 255) / 256, 256>>>(tdhW, tdxW);
    pre_gh_kernel<<<Bsz * Tt / 8, 256>>>(deltas, tdhB);
    pre_alpha_kernel<<<Bsz * Tt / 8, 256>>>(deltas, masks, tdxB, wcW, wcB);

    static int zsm = 64 * 256 * 4 + 16 * 128 * 4 + 256 * 4;  // ~73.25 KB
    cudaFuncSetAttribute(pre_z_kernel, cudaFuncAttributeMaxDynamicSharedMemorySize, zsm);
    pre_z_kernel<<<dim3(4, 8, Bsz / 2), 256, zsm>>>(masks, lstmK, lstmB);

    cudaFuncSetAttribute(rits_kernel, cudaFuncAttributeMaxDynamicSharedMemorySize,
                         (int)sizeof(Smem));
    rits_kernel<<<GRID, NT, sizeof(Smem)>>>(
        values, masks, histW, histB, frW, frB,
        lstmK, lstmRK, outW, outB, yout, impout);
}

// round 5
// speedup vs baseline: 1.2873x; 1.0002x over previous
#include <cuda_runtime.h>
#include <cstdint>

#define Bsz 1024
#define Tt  128
#define Dd  64
#define Hh  256
#define MB  8
#define NT  512
#define GRID 128

typedef unsigned long long u64;

// ------------------- device scratch (precomputed, per call) -------------------
__device__ float tdhT_g[Dd * Hh];                    // td_h_W^T  [k][c]
__device__ float tdxT_g[Dd * Dd];                    // td_x_W^T  [k][j]
__device__ float Gh_g[Bsz * Tt * Hh];                // gamma_h   [b*T+t][256]
__device__ float alpha_g[Bsz * Tt * Dd];             // alpha     [b*T+t][64]
__device__ float zprep_g[(Bsz / 2) * Tt * 1024 * 2]; // lstm_b + m@Wm, paired (b even, b odd)

__device__ __forceinline__ u64 dup2(float w) {
    u64 r; asm("mov.b64 %0, {%1,%1};" : "=l"(r) : "f"(w)); return r;
}
__device__ __forceinline__ void upk2(u64 v, float& lo, float& hi) {
    asm("mov.b64 {%0,%1}, %2;" : "=f"(lo), "=f"(hi) : "l"(v));
}
__device__ __forceinline__ u64 fma2(u64 a, u64 b, u64 c) {
    u64 d; asm("fma.rn.f32x2 %0, %1, %2, %3;" : "=l"(d) : "l"(a), "l"(b), "l"(c)); return d;
}
__device__ __forceinline__ u64 add2(u64 a, u64 b) {
    u64 d; asm("add.rn.f32x2 %0, %1, %2;" : "=l"(d) : "l"(a), "l"(b)); return d;
}
__device__ __forceinline__ float sigf(float x) {
    return __fdividef(1.f, 1.f + __expf(-x));
}
__device__ __forceinline__ float tanhfast(float x) {
    return __fdividef(2.f, 1.f + __expf(-2.f * x)) - 1.f;
}

// ============================ precompute kernels ============================

__global__ void transpose_kernel(const float* __restrict__ tdhW,
                                 const float* __restrict__ tdxW) {
    int idx = blockIdx.x * 256 + threadIdx.x;
    if (idx < Hh * Dd) {                       // tdhW (256,64) -> [k][c]
        int c = idx >> 6, k = idx & 63;
        tdhT_g[k * Hh + c] = tdhW[idx];
    } else if (idx < Hh * Dd + Dd * Dd) {      // tdxW (64,64) -> [k][j]
        int e = idx - Hh * Dd;
        int j = e >> 6, k = e & 63;
        tdxT_g[k * Dd + j] = tdxW[e];
    }
}

// gamma_h = exp(-relu(d @ td_h_W^T + b)) for all (b,t). 8 rows/CTA.
__global__ void __launch_bounds__(256) pre_gh_kernel(
    const float* __restrict__ deltas, const float* __restrict__ tdhB)
{
    __shared__ float dp[4 * Dd * 2];   // paired rows
    const int tid = threadIdx.x;
    const int row0 = blockIdx.x * 8;
    for (int e = tid; e < 8 * Dd; e += 256) {
        int r = e >> 6, k = e & 63;
        dp[(r >> 1) * 128 + k * 2 + (r & 1)] = deltas[(row0 + r) * Dd + k];
    }
    __syncthreads();
    const int c = tid;
    u64 a[4];
    #pragma unroll
    for (int p = 0; p < 4; p++) a[p] = 0ULL;
    #pragma unroll 4
    for (int k = 0; k < Dd; k++) {
        u64 wd = dup2(tdhT_g[k * Hh + c]);
        #pragma unroll
        for (int p = 0; p < 4; p++)
            a[p] = fma2(*(const u64*)(dp + p * 128 + k * 2), wd, a[p]);
    }
    float bb = tdhB[c];
    #pragma unroll
    for (int p = 0; p < 4; p++) {
        float a0, a1; upk2(a[p], a0, a1);
        Gh_g[(row0 + 2 * p)     * Hh + c] = __expf(-fmaxf(a0 + bb, 0.f));
        Gh_g[(row0 + 2 * p + 1) * Hh + c] = __expf(-fmaxf(a1 + bb, 0.f));
    }
}

// gamma_x then alpha for all (b,t). 8 rows/CTA.
__global__ void __launch_bounds__(256) pre_alpha_kernel(
    const float* __restrict__ deltas, const float* __restrict__ masks,
    const float* __restrict__ tdxB,
    const float* __restrict__ wcW, const float* __restrict__ wcB)
{
    __shared__ float dp[4 * Dd * 2], mp[4 * Dd * 2], gxp[4 * Dd * 2];
    const int tid = threadIdx.x;
    const int row0 = blockIdx.x * 8;
    for (int e = tid; e < 8 * Dd; e += 256) {
        int r = e >> 6, k = e & 63;
        dp[(r >> 1) * 128 + k * 2 + (r & 1)] = deltas[(row0 + r) * Dd + k];
        mp[(r >> 1) * 128 + k * 2 + (r & 1)] = masks[(row0 + r) * Dd + k];
    }
    __syncthreads();
    const int j = tid & 63, pg = tid >> 6;
    u64 g = dup2(tdxB[j]);
    #pragma unroll 4
    for (int k = 0; k < Dd; k++)
        g = fma2(*(const u64*)(dp + pg * 128 + k * 2), dup2(tdxT_g[k * Dd + j]), g);
    float g0, g1; upk2(g, g0, g1);
    gxp[pg * 128 + j * 2 + 0] = __expf(-fmaxf(g0, 0.f));
    gxp[pg * 128 + j * 2 + 1] = __expf(-fmaxf(g1, 0.f));
    __syncthreads();
    u64 al = dup2(wcB[j]);
    #pragma unroll 4
    for (int k = 0; k < Dd; k++) {
        al = fma2(*(const u64*)(gxp + pg * 128 + k * 2), dup2(wcW[k * Dd + j]), al);
        al = fma2(*(const u64*)(mp  + pg * 128 + k * 2), dup2(wcW[(Dd + k) * Dd + j]), al);
    }
    float a0, a1; upk2(al, a0, a1);
    alpha_g[(row0 + 2 * pg)     * Dd + j] = a0;
    alpha_g[(row0 + 2 * pg + 1) * Dd + j] = a1;
}

// zpre = lstm_b + m @ lstm_k[64:128], stored pair-interleaved by (b even, b odd).
// grid (4 col-tiles, 8 t-blocks, 512 b-pairs), NT=256, dyn smem 76KB.
__global__ void __launch_bounds__(256) pre_z_kernel(
    const float* __restrict__ masks, const float* __restrict__ lstmK,
    const float* __restrict__ lstmB)
{
    extern __shared__ float psm[];
    float* W  = psm;               // [64][256]
    float* mp = W + 64 * 256;      // [16 t][64 k][2 par]
    float* lb = mp + 16 * 128;     // [256]
    const int tid = threadIdx.x;
    const int c0 = blockIdx.x * 256;
    const int t0 = blockIdx.y * 16;
    const int bp = blockIdx.z;

    for (int e = tid; e < 64 * 256; e += 256) {
        int k = e >> 8, c = e & 255;
        W[e] = lstmK[(Dd + k) * 1024 + c0 + c];
    }
    if (tid < 256) lb[tid] = lstmB[c0 + tid];
    #pragma unroll
    for (int par = 0; par < 2; par++)
        for (int e = tid; e < 16 * 64; e += 256) {
            int tt = e >> 6, k = e & 63;
            mp[tt * 128 + k * 2 + par] = masks[((2 * bp + par) * Tt + t0 + tt) * Dd + k];
        }
    __syncthreads();

    const int cq = tid & 63;   // 4 cols: c0 + cq*4 ..
    const int pg = tid >> 6;   // 4 t's:  t0 + pg*4 ..
    u64 acc[4][4];
    #pragma unroll
    for (int tt = 0; tt < 4; tt++)
        #pragma unroll
        for (int c = 0; c < 4; c++) acc[tt][c] = 0ULL;

    #pragma unroll 2
    for (int k = 0; k < Dd; k++) {
        float4 w = *(const float4*)(W + k * 256 + cq * 4);
        u64 w0 = dup2(w.x), w1 = dup2(w.y), w2 = dup2(w.z), w3 = dup2(w.w);
        #pragma unroll
        for (int tt = 0; tt < 4; tt++) {
            u64 m2 = *(const u64*)(mp + (pg * 4 + tt) * 128 + k * 2);
            acc[tt][0] = fma2(m2, w0, acc[tt][0]);
            acc[tt][1] = fma2(m2, w1, acc[tt][1]);
            acc[tt][2] = fma2(m2, w2, acc[tt][2]);
            acc[tt][3] = fma2(m2, w3, acc[tt][3]);
        }
    }
    float4 lbv = *(const float4*)(lb + cq * 4);
    u64 lb0 = dup2(lbv.x), lb1 = dup2(lbv.y), lb2 = dup2(lbv.z), lb3 = dup2(lbv.w);
    #pragma unroll
    for (int tt = 0; tt < 4; tt++) {
        int tg = t0 + pg * 4 + tt;
        int col = c0 + cq * 4;
        u64* dst = (u64*)(zprep_g + ((size_t)(bp * Tt + tg) * 1024 + col) * 2);
        dst[0] = add2(acc[tt][0], lb0);
        dst[1] = add2(acc[tt][1], lb1);
        dst[2] = add2(acc[tt][2], lb2);
        dst[3] = add2(acc[tt][3], lb3);
    }
}

// ============================ main recurrent kernel ============================

struct __align__(16) Smem {
    float hist[Hh * Dd];      // 64 KB
    float frT[Dd * Dd];       // 16 KB
    float hp[4 * 2 * Hh];     //  8 KB  h paired [p][k*2+par]
    float cs[MB * Hh];        //  8 KB
    float zp[4 * 2 * 4 * Hh]; // 32 KB  gate acts (alias: x_h partials)
    float gh[MB * Hh];        //  8 KB  G_h[t+1] staging
    float xs[MB * Dd], ms[MB * Dd];
    float alp[4 * 2 * Dd];
    float xcp[4 * 2 * Dd], xhp[4 * 2 * Dd], ccp[4 * 2 * Dd];
    float hist_b[Dd], fr_b[Dd];
};

template <int STRIDE>
__device__ __forceinline__ void eblk(const float* src, int k0,
                                     float2 w0, float2 w1, u64 (&acc)[4][2]) {
    u64 wa0 = dup2(w0.x), wb0 = dup2(w0.y);
    u64 wa1 = dup2(w1.x), wb1 = dup2(w1.y);
    #pragma unroll
    for (int p = 0; p < 4; p++) {
        float4 hv = *(const float4*)(src + p * STRIDE + k0 * 2);
        u64 h0 = ((const u64*)&hv)[0];
        u64 h1 = ((const u64*)&hv)[1];
        acc[p][0] = fma2(h0, wa0, acc[p][0]);
        acc[p][1] = fma2(h0, wb0, acc[p][1]);
        acc[p][0] = fma2(h1, wa1, acc[p][0]);
        acc[p][1] = fma2(h1, wb1, acc[p][1]);
    }
}

__global__ void __launch_bounds__(NT, 1) rits_kernel(
    const float* __restrict__ values, const float* __restrict__ masks,
    const float* __restrict__ histW, const float* __restrict__ histB,
    const float* __restrict__ frW, const float* __restrict__ frB,
    const float* __restrict__ lstmK, const float* __restrict__ lstmRK,
    const float* __restrict__ outW, const float* __restrict__ outB,
    float* __restrict__ yout, float* __restrict__ impout)
{
    extern __shared__ char smem_raw[];
    Smem& sm = *reinterpret_cast<Smem*>(smem_raw);

    const int t  = threadIdx.x;
    const int b0 = blockIdx.x * MB;

    // ---- stage resident weights & init state ----
    for (int e = t; e < Hh * Dd; e += NT) sm.hist[e] = histW[e];
    for (int e = t; e < Dd * Dd; e += NT) {
        int k = e >> 6, jj = e & 63;
        sm.frT[e] = frW[jj * Dd + k];
    }
    if (t < Dd) { sm.hist_b[t] = histB[t]; sm.fr_b[t] = frB[t]; }
    for (int e = t; e < MB * Hh; e += NT) sm.cs[e] = 0.f;
    for (int e = t; e < 4 * 2 * Hh; e += NT) sm.hp[e] = 0.f;
    {   // step-0 inputs + alpha[0]
        int r = t >> 6, jj = t & 63;
        int off = ((b0 + r) * Tt + 0) * Dd + jj;
        sm.xs[t] = values[off]; sm.ms[t] = masks[off];
        int j = t & 63, p = (t >> 6) & 3, par = t >> 8;
        sm.alp[p * 128 + j * 2 + par] = alpha_g[((b0 + 2 * p + par) * Tt + 0) * Dd + j];
    }
    __syncthreads();

    float pf_x[2], pf_m[2], pf_a0, pf_a1;   // wg1 prefetch regs

    for (int step = 0; step < Tt; ++step) {
        // ---- P1 (all): x_h partials, k-split 8-way, into zp alias ----
        float2* cpart = (float2*)sm.zp;
        {
            const int j = t & 63, kq = t >> 6;
            u64 a[4];
            #pragma unroll
            for (int p = 0; p < 4; p++) a[p] = 0ULL;
            const int k0 = kq * 32;
            #pragma unroll 4
            for (int kk = 0; kk < 32; kk++) {
                int k = k0 + kk;
                u64 wd = dup2(sm.hist[k * Dd + j]);
                #pragma unroll
                for (int p = 0; p < 4; p++)
                    a[p] = fma2(*(const u64*)(sm.hp + p * 512 + k * 2), wd, a[p]);
            }
            #pragma unroll
            for (int p = 0; p < 4; p++) {
                float a0, a1; upk2(a[p], a0, a1);
                cpart[(kq * 4 + p) * 64 + j] = make_float2(a0, a1);
            }
        }
        __syncthreads();

        // ---- P3: wg0 {reduce -> x_c; z_h -> c_c -> impout} | wg1 {prefetch} --
        if (t < 256) {
            const int j = t & 63, p = t >> 6;
            const float* cp = (const float*)cpart;
            float xh[2], xc[2];
            #pragma unroll
            for (int par = 0; par < 2; par++) {
                float s = 0.f;
                #pragma unroll
                for (int kq = 0; kq < 8; kq++)
                    s += cp[((kq * 4 + p) * 64 + j) * 2 + par];
                xh[par] = s + sm.hist_b[j];
                int r = 2 * p + par;
                float m = sm.ms[r * Dd + j], x = sm.xs[r * Dd + j];
                xc[par] = m * x + (1.f - m) * xh[par];
                sm.xcp[p * 128 + j * 2 + par] = xc[par];
                sm.xhp[p * 128 + j * 2 + par] = xh[par];
            }
            asm volatile("bar.sync 1, 256;" ::: "memory");
            // z_h, alpha-combine, imputation
            u64 z = dup2(sm.fr_b[j]);
            #pragma unroll 4
            for (int k = 0; k < Dd; k++)
                z = fma2(*(const u64*)(sm.xcp + p * 128 + k * 2),
                         dup2(sm.frT[k * Dd + j]), z);
            float z0, z1; upk2(z, z0, z1);
            float2 al = *(const float2*)(sm.alp + p * 128 + j * 2);
            int r0 = 2 * p, r1 = r0 + 1;
            float m0 = sm.ms[r0 * Dd + j], m1 = sm.ms[r1 * Dd + j];
            float x0 = sm.xs[r0 * Dd + j], x1 = sm.xs[r1 * Dd + j];
            float ch0 = al.x * z0 + (1.f - al.x) * xh[0];
            float ch1 = al.y * z1 + (1.f - al.y) * xh[1];
            float cc0 = m0 * x0 + (1.f - m0) * ch0;
            float cc1 = m1 * x1 + (1.f - m1) * ch1;
            *(float2*)(sm.ccp + p * 128 + j * 2) = make_float2(cc0, cc1);
            impout[(r0 + b0) * Tt * Dd + step * Dd + j] = cc0;
            impout[(r1 + b0) * Tt * Dd + step * Dd + j] = cc1;
        } else if (step + 1 < Tt) {
            const int u = t - 256;
            #pragma unroll
            for (int s = 0; s < 2; s++) {
                int e = u + s * 256;
                int r = e >> 6, jj = e & 63;
                int off = ((b0 + r) * Tt + (step + 1)) * Dd + jj;
                pf_x[s] = values[off]; pf_m[s] = masks[off];
            }
            {
                int j = u & 63, rp = u >> 6;
                pf_a0 = alpha_g[((b0 + 2 * rp)     * Tt + step + 1) * Dd + j];
                pf_a1 = alpha_g[((b0 + 2 * rp + 1) * Tt + step + 1) * Dd + j];
            }
            {
                int r = u >> 5, c0 = (u & 31) * 8;
                const float* gsrc = Gh_g + ((b0 + r) * Tt + (step + 1)) * Hh + c0;
                float4 g0 = *(const float4*)gsrc;
                float4 g1 = *(const float4*)(gsrc + 4);
                *(float4*)(sm.gh + r * Hh + c0)     = g0;
                *(float4*)(sm.gh + r * Hh + c0 + 4) = g1;
            }
        }
        __syncthreads();

        // ---- P4 (all): z = zpre + c_c@Wk_cc + h@Wrk ; activations ----
        {
            // issue zpre loads up front, consume at the end
            u64 zin[4][2];
            const float4* zp4 = (const float4*)zprep_g;
            #pragma unroll
            for (int p = 0; p < 4; p++) {
                float4 v = zp4[((size_t)(b0 / 2 + p) * Tt + step) * 512 + t];
                zin[p][0] = ((const u64*)&v)[0];
                zin[p][1] = ((const u64*)&v)[1];
            }
            u64 acc[4][2];
            #pragma unroll
            for (int p = 0; p < 4; p++) { acc[p][0] = 0ULL; acc[p][1] = 0ULL; }

            // recurrent part, k = 0..255, 4k-deep weight pipeline
            const float2* rk2 = (const float2*)lstmRK;
            float2 wA0 = rk2[t], wA1 = rk2[512 + t];
            float2 wB0 = rk2[1024 + t], wB1 = rk2[1536 + t];
            #pragma unroll 2
            for (int k = 0; k < Hh; k += 4) {
                int kn = (k + 4) & 255;
                float2 nA0 = rk2[kn * 512 + t],       nA1 = rk2[(kn + 1) * 512 + t];
                float2 nB0 = rk2[(kn + 2) * 512 + t], nB1 = rk2[(kn + 3) * 512 + t];
                eblk<512>(sm.hp, k,     wA0, wA1, acc);
                eblk<512>(sm.hp, k + 2, wB0, wB1, acc);
                wA0 = nA0; wA1 = nA1; wB0 = nB0; wB1 = nB1;
            }
            // c_c part, k = 0..63
            const float2* kk2 = (const float2*)lstmK;
            wA0 = kk2[t]; wA1 = kk2[512 + t];
            wB0 = kk2[1024 + t]; wB1 = kk2[1536 + t];
            #pragma unroll 2
            for (int k = 0; k < Dd; k += 4) {
                int kn = (k + 4) & 63;
                float2 nA0 = kk2[kn * 512 + t],       nA1 = kk2[(kn + 1) * 512 + t];
                float2 nB0 = kk2[(kn + 2) * 512 + t], nB1 = kk2[(kn + 3) * 512 + t];
                eblk<128>(sm.ccp, k,     wA0, wA1, acc);
                eblk<128>(sm.ccp, k + 2, wB0, wB1, acc);
                wA0 = nA0; wA1 = nA1; wB0 = nB0; wB1 = nB1;
            }
            const int gate = t >> 7;
            #pragma unroll
            for (int p = 0; p < 4; p++) {
                #pragma unroll
                for (int q = 0; q < 2; q++) {
                    u64 zv = add2(acc[p][q], zin[p][q]);
                    float v0, v1; upk2(zv, v0, v1);
                    float a0, a1;
                    if (gate == 2) { a0 = tanhfast(v0); a1 = tanhfast(v1); }
                    else           { a0 = sigf(v0);     a1 = sigf(v1);     }
                    int col = 2 * t + q;
                    *(float2*)(sm.zp + p * 2048 + col * 2) = make_float2(a0, a1);
                }
            }
        }
        __syncthreads();

        // ---- P5: wg0 {c,h update (+ fused next-step decay)} | wg1 {commit} --
        if (t < 256) {
            int r = t >> 5;
            int p = r >> 1, par = r & 1;
            int c0 = (t & 31) * 8;
            bool last = (step == Tt - 1);
            float4 gA = *(const float4*)(sm.gh + r * Hh + c0);
            float4 gB = *(const float4*)(sm.gh + r * Hh + c0 + 4);
            float gv8[8] = {gA.x, gA.y, gA.z, gA.w, gB.x, gB.y, gB.z, gB.w};
            #pragma unroll
            for (int cc = 0; cc < 8; cc++) {
                int c = c0 + cc;
                float iv = sm.zp[p * 2048 + (0 * Hh + c) * 2 + par];
                float fv = sm.zp[p * 2048 + (1 * Hh + c) * 2 + par];
                float gg = sm.zp[p * 2048 + (2 * Hh + c) * 2 + par];
                float ov = sm.zp[p * 2048 + (3 * Hh + c) * 2 + par];
                float cold = sm.cs[r * Hh + c];
                float cnew = fv * cold + iv * gg;
                sm.cs[r * Hh + c] = cnew;
                float hh = ov * tanhfast(cnew);
                if (!last) hh *= gv8[cc];
                sm.hp[p * 512 + c * 2 + par] = hh;
            }
        } else if (step + 1 < Tt) {
            const int u = t - 256;
            #pragma unroll
            for (int s = 0; s < 2; s++) {
                int e = u + s * 256;
                sm.xs[e] = pf_x[s]; sm.ms[e] = pf_m[s];
            }
            int j = u & 63, rp = u >> 6;
            *(float2*)(sm.alp + rp * 128 + j * 2) = make_float2(pf_a0, pf_a1);
        }
        __syncthreads();
    }

    // ---- final: y = h @ out_W + out_b ----
    {
        int w = t >> 5, lane = t & 31;
        if (w < MB) {
            float s = 0.f;
            for (int k = lane; k < Hh; k += 32)
                s += sm.hp[(w >> 1) * 512 + k * 2 + (w & 1)] * outW[k];
            #pragma unroll
            for (int o = 16; o > 0; o >>= 1)
                s += __shfl_down_sync(0xffffffffu, s, o);
            if (lane == 0) yout[b0 + w] = s + outB[0];
        }
    }
}

// ================================ launcher ================================

extern "C" void kernel_launch(void* const* d_in, const int* in_sizes, int n_in,
                              void* d_out, int out_size) {
    const float* values = (const float*)d_in[0];
    const float* masks  = (const float*)d_in[1];
    const float* deltas = (const float*)d_in[2];
    const float* tdhW   = (const float*)d_in[3];
    const float* tdhB   = (const float*)d_in[4];
    const float* tdxW   = (const float*)d_in[5];
    const float* tdxB   = (const float*)d_in[6];
    const float* histW  = (const float*)d_in[7];
    const float* histB  = (const float*)d_in[8];
    const float* frW    = (const float*)d_in[9];
    const float* frB    = (const float*)d_in[10];
    const float* wcW    = (const float*)d_in[11];
    const float* wcB    = (const float*)d_in[12];
    const float* lstmK  = (const float*)d_in[13];
    const float* lstmRK = (const float*)d_in[14];
    const float* lstmB  = (const float*)d_in[15];
    const float* outW   = (const float*)d_in[16];
    const float* outB   = (const float*)d_in[17];

    float* yout   = (float*)d_out;       // y_h [B,1] first
    float* impout = yout + Bsz;          // imputations [B,T,D]

    transpose_kernel<<<(Hh * Dd + Dd * Dd + 255) / 256, 256>>>(tdhW, tdxW);
    pre_gh_kernel<<<Bsz * Tt / 8, 256>>>(deltas, tdhB);
    pre_alpha_kernel<<<Bsz * Tt / 8, 256>>>(deltas, masks, tdxB, wcW, wcB);

    static int zsm = 64 * 256 * 4 + 16 * 128 * 4 + 256 * 4;  // ~73.25 KB
    cudaFuncSetAttribute(pre_z_kernel, cudaFuncAttributeMaxDynamicSharedMemorySize, zsm);
    pre_z_kernel<<<dim3(4, 8, Bsz / 2), 256, zsm>>>(masks, lstmK, lstmB);

    cudaFuncSetAttribute(rits_kernel, cudaFuncAttributeMaxDynamicSharedMemorySize,
                         (int)sizeof(Smem));
    rits_kernel<<<GRID, NT, sizeof(Smem)>>>(
        values, masks, histW, histB, frW, frB,
        lstmK, lstmRK, outW, outB, yout, impout);
}

// round 6
// speedup vs baseline: 1.3151x; 1.0216x over previous
#include <cuda_runtime.h>
#include <cstdint>

#define Bsz 1024
#define Tt  128
#define Dd  64
#define Hh  256
#define MB  8
#define NT  512
#define GRID 128

typedef unsigned long long u64;

// ------------------- device scratch (precomputed, per call) -------------------
__device__ float tdhT_g[Dd * Hh];                    // td_h_W^T  [k][c]
__device__ float tdxT_g[Dd * Dd];                    // td_x_W^T  [k][j]
__device__ float Gh_g[Bsz * Tt * Hh];                // gamma_h   [b*T+t][256]
__device__ float alpha_g[Bsz * Tt * Dd];             // alpha     [b*T+t][64]
__device__ float zprep_g[(Bsz / 2) * Tt * 1024 * 2]; // lstm_b + m@Wm, paired

__device__ __forceinline__ u64 dup2(float w) {
    u64 r; asm("mov.b64 %0, {%1,%1};" : "=l"(r) : "f"(w)); return r;
}
__device__ __forceinline__ void upk2(u64 v, float& lo, float& hi) {
    asm("mov.b64 {%0,%1}, %2;" : "=f"(lo), "=f"(hi) : "l"(v));
}
__device__ __forceinline__ u64 fma2(u64 a, u64 b, u64 c) {
    u64 d; asm("fma.rn.f32x2 %0, %1, %2, %3;" : "=l"(d) : "l"(a), "l"(b), "l"(c)); return d;
}
__device__ __forceinline__ u64 add2(u64 a, u64 b) {
    u64 d; asm("add.rn.f32x2 %0, %1, %2;" : "=l"(d) : "l"(a), "l"(b)); return d;
}
__device__ __forceinline__ float sigf(float x) {
    return __fdividef(1.f, 1.f + __expf(-x));
}
__device__ __forceinline__ float tanhfast(float x) {
    return __fdividef(2.f, 1.f + __expf(-2.f * x)) - 1.f;
}

// ============================ precompute kernels ============================

__global__ void transpose_kernel(const float* __restrict__ tdhW,
                                 const float* __restrict__ tdxW) {
    int idx = blockIdx.x * 256 + threadIdx.x;
    if (idx < Hh * Dd) {                       // tdhW (256,64) -> [k][c]
        int c = idx >> 6, k = idx & 63;
        tdhT_g[k * Hh + c] = tdhW[idx];
    } else if (idx < Hh * Dd + Dd * Dd) {      // tdxW (64,64) -> [k][j]
        int e = idx - Hh * Dd;
        int j = e >> 6, k = e & 63;
        tdxT_g[k * Dd + j] = tdxW[e];
    }
}

// merged: gamma_h AND (gamma_x -> alpha) for 8 rows/CTA (shares delta/mask loads)
__global__ void __launch_bounds__(256) pre_ga_kernel(
    const float* __restrict__ deltas, const float* __restrict__ masks,
    const float* __restrict__ tdhB, const float* __restrict__ tdxB,
    const float* __restrict__ wcW, const float* __restrict__ wcB)
{
    __shared__ float dp[4 * Dd * 2], mp[4 * Dd * 2], gxp[4 * Dd * 2];
    const int tid = threadIdx.x;
    const int row0 = blockIdx.x * 8;
    for (int e = tid; e < 8 * Dd; e += 256) {
        int r = e >> 6, k = e & 63;
        dp[(r >> 1) * 128 + k * 2 + (r & 1)] = deltas[(row0 + r) * Dd + k];
        mp[(r >> 1) * 128 + k * 2 + (r & 1)] = masks[(row0 + r) * Dd + k];
    }
    __syncthreads();

    // ---- gamma_h: each thread one column c ----
    {
        const int c = tid;
        u64 a[4];
        #pragma unroll
        for (int p = 0; p < 4; p++) a[p] = 0ULL;
        #pragma unroll 4
        for (int k = 0; k < Dd; k++) {
            u64 wd = dup2(tdhT_g[k * Hh + c]);
            #pragma unroll
            for (int p = 0; p < 4; p++)
                a[p] = fma2(*(const u64*)(dp + p * 128 + k * 2), wd, a[p]);
        }
        float bb = tdhB[c];
        #pragma unroll
        for (int p = 0; p < 4; p++) {
            float a0, a1; upk2(a[p], a0, a1);
            Gh_g[(row0 + 2 * p)     * Hh + c] = __expf(-fmaxf(a0 + bb, 0.f));
            Gh_g[(row0 + 2 * p + 1) * Hh + c] = __expf(-fmaxf(a1 + bb, 0.f));
        }
    }

    // ---- gamma_x then alpha ----
    const int j = tid & 63, pg = tid >> 6;
    u64 g = dup2(tdxB[j]);
    #pragma unroll 4
    for (int k = 0; k < Dd; k++)
        g = fma2(*(const u64*)(dp + pg * 128 + k * 2), dup2(tdxT_g[k * Dd + j]), g);
    float g0, g1; upk2(g, g0, g1);
    gxp[pg * 128 + j * 2 + 0] = __expf(-fmaxf(g0, 0.f));
    gxp[pg * 128 + j * 2 + 1] = __expf(-fmaxf(g1, 0.f));
    __syncthreads();
    u64 al = dup2(wcB[j]);
    #pragma unroll 4
    for (int k = 0; k < Dd; k++) {
        al = fma2(*(const u64*)(gxp + pg * 128 + k * 2), dup2(wcW[k * Dd + j]), al);
        al = fma2(*(const u64*)(mp  + pg * 128 + k * 2), dup2(wcW[(Dd + k) * Dd + j]), al);
    }
    float a0, a1; upk2(al, a0, a1);
    alpha_g[(row0 + 2 * pg)     * Dd + j] = a0;
    alpha_g[(row0 + 2 * pg + 1) * Dd + j] = a1;
}

// zpre = lstm_b + m @ lstm_k[64:128], pair-interleaved (b even, b odd).
// grid (4 col-tiles, 512 b-pairs): W + bias staged ONCE, reused over all 128 t.
__global__ void __launch_bounds__(256) pre_z_kernel(
    const float* __restrict__ masks, const float* __restrict__ lstmK,
    const float* __restrict__ lstmB)
{
    extern __shared__ float psm[];
    float* W  = psm;               // [64][256]
    float* lb = W + 64 * 256;      // [256]
    float* mp = lb + 256;          // [16 t][64 k][2 par]
    const int tid = threadIdx.x;
    const int c0 = blockIdx.x * 256;
    const int bp = blockIdx.y;

    for (int e = tid; e < 64 * 256; e += 256) {
        int k = e >> 8, c = e & 255;
        W[e] = lstmK[(Dd + k) * 1024 + c0 + c];
    }
    lb[tid] = lstmB[c0 + tid];

    const int cq = tid & 63;   // 4 cols: c0 + cq*4 ..
    const int pg = tid >> 6;   // 4 t's per chunk: pg*4 ..

    for (int t0 = 0; t0 < Tt; t0 += 16) {
        __syncthreads();   // also covers W/lb on first iteration; mp reuse after
        #pragma unroll
        for (int par = 0; par < 2; par++)
            for (int e = tid; e < 16 * 64; e += 256) {
                int tt = e >> 6, k = e & 63;
                mp[tt * 128 + k * 2 + par] =
                    masks[((2 * bp + par) * Tt + t0 + tt) * Dd + k];
            }
        __syncthreads();

        u64 acc[4][4];
        #pragma unroll
        for (int tt = 0; tt < 4; tt++)
            #pragma unroll
            for (int c = 0; c < 4; c++) acc[tt][c] = 0ULL;

        #pragma unroll 2
        for (int k = 0; k < Dd; k++) {
            float4 w = *(const float4*)(W + k * 256 + cq * 4);
            u64 w0 = dup2(w.x), w1 = dup2(w.y), w2 = dup2(w.z), w3 = dup2(w.w);
            #pragma unroll
            for (int tt = 0; tt < 4; tt++) {
                u64 m2 = *(const u64*)(mp + (pg * 4 + tt) * 128 + k * 2);
                acc[tt][0] = fma2(m2, w0, acc[tt][0]);
                acc[tt][1] = fma2(m2, w1, acc[tt][1]);
                acc[tt][2] = fma2(m2, w2, acc[tt][2]);
                acc[tt][3] = fma2(m2, w3, acc[tt][3]);
            }
        }
        float4 lbv = *(const float4*)(lb + cq * 4);
        u64 lb0 = dup2(lbv.x), lb1 = dup2(lbv.y), lb2 = dup2(lbv.z), lb3 = dup2(lbv.w);
        #pragma unroll
        for (int tt = 0; tt < 4; tt++) {
            int tg = t0 + pg * 4 + tt;
            int col = c0 + cq * 4;
            u64* dst = (u64*)(zprep_g + ((size_t)(bp * Tt + tg) * 1024 + col) * 2);
            dst[0] = add2(acc[tt][0], lb0);
            dst[1] = add2(acc[tt][1], lb1);
            dst[2] = add2(acc[tt][2], lb2);
            dst[3] = add2(acc[tt][3], lb3);
        }
    }
}

// ============================ main recurrent kernel ============================

struct __align__(16) Smem {
    float hist[Hh * Dd];      // 64 KB
    float frT[Dd * Dd];       // 16 KB
    float hp[4 * 2 * Hh];     //  8 KB  h paired [p][k*2+par]
    float cs[MB * Hh];        //  8 KB
    float zp[4 * 2 * 4 * Hh]; // 32 KB  gate acts (alias: x_h partials)
    float gh[MB * Hh];        //  8 KB  G_h[t+1] staging
    float xs[MB * Dd], ms[MB * Dd];
    float alp[4 * 2 * Dd];
    float xcp[4 * 2 * Dd], xhp[4 * 2 * Dd], ccp[4 * 2 * Dd];
    float hist_b[Dd], fr_b[Dd];
};

template <int STRIDE>
__device__ __forceinline__ void eblk(const float* src, int k0,
                                     float2 w0, float2 w1, u64 (&acc)[4][2]) {
    u64 wa0 = dup2(w0.x), wb0 = dup2(w0.y);
    u64 wa1 = dup2(w1.x), wb1 = dup2(w1.y);
    #pragma unroll
    for (int p = 0; p < 4; p++) {
        float4 hv = *(const float4*)(src + p * STRIDE + k0 * 2);
        u64 h0 = ((const u64*)&hv)[0];
        u64 h1 = ((const u64*)&hv)[1];
        acc[p][0] = fma2(h0, wa0, acc[p][0]);
        acc[p][1] = fma2(h0, wb0, acc[p][1]);
        acc[p][0] = fma2(h1, wa1, acc[p][0]);
        acc[p][1] = fma2(h1, wb1, acc[p][1]);
    }
}

__global__ void __launch_bounds__(NT, 1) rits_kernel(
    const float* __restrict__ values, const float* __restrict__ masks,
    const float* __restrict__ histW, const float* __restrict__ histB,
    const float* __restrict__ frW, const float* __restrict__ frB,
    const float* __restrict__ lstmK, const float* __restrict__ lstmRK,
    const float* __restrict__ outW, const float* __restrict__ outB,
    float* __restrict__ yout, float* __restrict__ impout)
{
    extern __shared__ char smem_raw[];
    Smem& sm = *reinterpret_cast<Smem*>(smem_raw);

    const int t  = threadIdx.x;
    const int b0 = blockIdx.x * MB;

    // ---- stage resident weights & init state ----
    for (int e = t; e < Hh * Dd; e += NT) sm.hist[e] = histW[e];
    for (int e = t; e < Dd * Dd; e += NT) {
        int k = e >> 6, jj = e & 63;
        sm.frT[e] = frW[jj * Dd + k];
    }
    if (t < Dd) { sm.hist_b[t] = histB[t]; sm.fr_b[t] = frB[t]; }
    for (int e = t; e < MB * Hh; e += NT) sm.cs[e] = 0.f;
    for (int e = t; e < 4 * 2 * Hh; e += NT) sm.hp[e] = 0.f;
    {   // step-0 inputs + alpha[0]
        int r = t >> 6, jj = t & 63;
        int off = ((b0 + r) * Tt + 0) * Dd + jj;
        sm.xs[t] = values[off]; sm.ms[t] = masks[off];
        int j = t & 63, p = (t >> 6) & 3, par = t >> 8;
        sm.alp[p * 128 + j * 2 + par] = alpha_g[((b0 + 2 * p + par) * Tt + 0) * Dd + j];
    }
    __syncthreads();

    float pf_x[2], pf_m[2], pf_a0, pf_a1;   // wg1 prefetch regs

    for (int step = 0; step < Tt; ++step) {
        // ---- P1 (all): x_h partials, k-split 8-way, into zp alias ----
        float2* cpart = (float2*)sm.zp;
        {
            const int j = t & 63, kq = t >> 6;
            u64 a[4];
            #pragma unroll
            for (int p = 0; p < 4; p++) a[p] = 0ULL;
            const int k0 = kq * 32;
            #pragma unroll 4
            for (int kk = 0; kk < 32; kk++) {
                int k = k0 + kk;
                u64 wd = dup2(sm.hist[k * Dd + j]);
                #pragma unroll
                for (int p = 0; p < 4; p++)
                    a[p] = fma2(*(const u64*)(sm.hp + p * 512 + k * 2), wd, a[p]);
            }
            #pragma unroll
            for (int p = 0; p < 4; p++) {
                float a0, a1; upk2(a[p], a0, a1);
                cpart[(kq * 4 + p) * 64 + j] = make_float2(a0, a1);
            }
        }
        __syncthreads();

        // ---- P3: wg0 {reduce -> x_c; z_h -> c_c -> impout} | wg1 {prefetch} --
        if (t < 256) {
            const int j = t & 63, p = t >> 6;
            const float* cp = (const float*)cpart;
            float xh[2], xc[2];
            #pragma unroll
            for (int par = 0; par < 2; par++) {
                float s = 0.f;
                #pragma unroll
                for (int kq = 0; kq < 8; kq++)
                    s += cp[((kq * 4 + p) * 64 + j) * 2 + par];
                xh[par] = s + sm.hist_b[j];
                int r = 2 * p + par;
                float m = sm.ms[r * Dd + j], x = sm.xs[r * Dd + j];
                xc[par] = m * x + (1.f - m) * xh[par];
                sm.xcp[p * 128 + j * 2 + par] = xc[par];
                sm.xhp[p * 128 + j * 2 + par] = xh[par];
            }
            asm volatile("bar.sync 1, 256;" ::: "memory");
            u64 z = dup2(sm.fr_b[j]);
            #pragma unroll 4
            for (int k = 0; k < Dd; k++)
                z = fma2(*(const u64*)(sm.xcp + p * 128 + k * 2),
                         dup2(sm.frT[k * Dd + j]), z);
            float z0, z1; upk2(z, z0, z1);
            float2 al = *(const float2*)(sm.alp + p * 128 + j * 2);
            int r0 = 2 * p, r1 = r0 + 1;
            float m0 = sm.ms[r0 * Dd + j], m1 = sm.ms[r1 * Dd + j];
            float x0 = sm.xs[r0 * Dd + j], x1 = sm.xs[r1 * Dd + j];
            float ch0 = al.x * z0 + (1.f - al.x) * xh[0];
            float ch1 = al.y * z1 + (1.f - al.y) * xh[1];
            float cc0 = m0 * x0 + (1.f - m0) * ch0;
            float cc1 = m1 * x1 + (1.f - m1) * ch1;
            *(float2*)(sm.ccp + p * 128 + j * 2) = make_float2(cc0, cc1);
            impout[(r0 + b0) * Tt * Dd + step * Dd + j] = cc0;
            impout[(r1 + b0) * Tt * Dd + step * Dd + j] = cc1;
        } else if (step + 1 < Tt) {
            const int u = t - 256;
            #pragma unroll
            for (int s = 0; s < 2; s++) {
                int e = u + s * 256;
                int r = e >> 6, jj = e & 63;
                int off = ((b0 + r) * Tt + (step + 1)) * Dd + jj;
                pf_x[s] = values[off]; pf_m[s] = masks[off];
            }
            {
                int j = u & 63, rp = u >> 6;
                pf_a0 = alpha_g[((b0 + 2 * rp)     * Tt + step + 1) * Dd + j];
                pf_a1 = alpha_g[((b0 + 2 * rp + 1) * Tt + step + 1) * Dd + j];
            }
            {
                int r = u >> 5, c0 = (u & 31) * 8;
                const float* gsrc = Gh_g + ((b0 + r) * Tt + (step + 1)) * Hh + c0;
                float4 g0 = *(const float4*)gsrc;
                float4 g1 = *(const float4*)(gsrc + 4);
                *(float4*)(sm.gh + r * Hh + c0)     = g0;
                *(float4*)(sm.gh + r * Hh + c0 + 4) = g1;
            }
        }
        __syncthreads();

        // ---- P4 (all): z = zpre + c_c@Wk_cc + h@Wrk ; distance-8 pipeline ----
        {
            u64 acc[4][2];
            #pragma unroll
            for (int p = 0; p < 4; p++) { acc[p][0] = 0ULL; acc[p][1] = 0ULL; }

            // ---- recurrent part, k = 0..255, weights prefetched 8 k ahead ----
            const float2* rk2 = (const float2*)lstmRK;
            float2 a0 = rk2[t],        a1 = rk2[512 + t];
            float2 a2 = rk2[1024 + t], a3 = rk2[1536 + t];
            float2 c0 = rk2[2048 + t], c1 = rk2[2560 + t];
            float2 c2 = rk2[3072 + t], c3 = rk2[3584 + t];
            #pragma unroll 2
            for (int k = 0; k < Hh; k += 8) {
                int kn = (k + 8) & 255;
                float2 na0 = rk2[kn * 512 + t],       na1 = rk2[(kn + 1) * 512 + t];
                float2 na2 = rk2[(kn + 2) * 512 + t], na3 = rk2[(kn + 3) * 512 + t];
                eblk<512>(sm.hp, k,     a0, a1, acc);
                eblk<512>(sm.hp, k + 2, a2, a3, acc);
                int km = (k + 12) & 255;
                float2 nc0 = rk2[km * 512 + t],       nc1 = rk2[(km + 1) * 512 + t];
                float2 nc2 = rk2[(km + 2) * 512 + t], nc3 = rk2[(km + 3) * 512 + t];
                eblk<512>(sm.hp, k + 4, c0, c1, acc);
                eblk<512>(sm.hp, k + 6, c2, c3, acc);
                a0 = na0; a1 = na1; a2 = na2; a3 = na3;
                c0 = nc0; c1 = nc1; c2 = nc2; c3 = nc3;
            }

            // ---- zpre loads issued here, consumed after cc part ----
            u64 zin[4][2];
            const float4* zp4 = (const float4*)zprep_g;
            #pragma unroll
            for (int p = 0; p < 4; p++) {
                float4 v = zp4[((size_t)(b0 / 2 + p) * Tt + step) * 512 + t];
                zin[p][0] = ((const u64*)&v)[0];
                zin[p][1] = ((const u64*)&v)[1];
            }

            // ---- c_c part, k = 0..63, same distance-8 pipeline ----
            const float2* kk2 = (const float2*)lstmK;
            a0 = kk2[t];        a1 = kk2[512 + t];
            a2 = kk2[1024 + t]; a3 = kk2[1536 + t];
            c0 = kk2[2048 + t]; c1 = kk2[2560 + t];
            c2 = kk2[3072 + t]; c3 = kk2[3584 + t];
            #pragma unroll 2
            for (int k = 0; k < Dd; k += 8) {
                int kn = (k + 8) & 63;
                float2 na0 = kk2[kn * 512 + t],       na1 = kk2[(kn + 1) * 512 + t];
                float2 na2 = kk2[(kn + 2) * 512 + t], na3 = kk2[(kn + 3) * 512 + t];
                eblk<128>(sm.ccp, k,     a0, a1, acc);
                eblk<128>(sm.ccp, k + 2, a2, a3, acc);
                int km = (k + 12) & 63;
                float2 nc0 = kk2[km * 512 + t],       nc1 = kk2[(km + 1) * 512 + t];
                float2 nc2 = kk2[(km + 2) * 512 + t], nc3 = kk2[(km + 3) * 512 + t];
                eblk<128>(sm.ccp, k + 4, c0, c1, acc);
                eblk<128>(sm.ccp, k + 6, c2, c3, acc);
                a0 = na0; a1 = na1; a2 = na2; a3 = na3;
                c0 = nc0; c1 = nc1; c2 = nc2; c3 = nc3;
            }

            const int gate = t >> 7;
            #pragma unroll
            for (int p = 0; p < 4; p++) {
                #pragma unroll
                for (int q = 0; q < 2; q++) {
                    u64 zv = add2(acc[p][q], zin[p][q]);
                    float v0, v1; upk2(zv, v0, v1);
                    float b0f, b1f;
                    if (gate == 2) { b0f = tanhfast(v0); b1f = tanhfast(v1); }
                    else           { b0f = sigf(v0);     b1f = sigf(v1);     }
                    int col = 2 * t + q;
                    *(float2*)(sm.zp + p * 2048 + col * 2) = make_float2(b0f, b1f);
                }
            }
        }
        __syncthreads();

        // ---- P5: wg0 {c,h update + fused next-step decay} | wg1 {commit} ----
        if (t < 256) {
            int r = t >> 5;
            int p = r >> 1, par = r & 1;
            int cb = (t & 31) * 8;
            bool last = (step == Tt - 1);
            float4 gA = *(const float4*)(sm.gh + r * Hh + cb);
            float4 gB = *(const float4*)(sm.gh + r * Hh + cb + 4);
            float gv8[8] = {gA.x, gA.y, gA.z, gA.w, gB.x, gB.y, gB.z, gB.w};
            #pragma unroll
            for (int cc = 0; cc < 8; cc++) {
                int c = cb + cc;
                float iv = sm.zp[p * 2048 + (0 * Hh + c) * 2 + par];
                float fv = sm.zp[p * 2048 + (1 * Hh + c) * 2 + par];
                float gg = sm.zp[p * 2048 + (2 * Hh + c) * 2 + par];
                float ov = sm.zp[p * 2048 + (3 * Hh + c) * 2 + par];
                float cold = sm.cs[r * Hh + c];
                float cnew = fv * cold + iv * gg;
                sm.cs[r * Hh + c] = cnew;
                float hh = ov * tanhfast(cnew);
                if (!last) hh *= gv8[cc];
                sm.hp[p * 512 + c * 2 + par] = hh;
            }
        } else if (step + 1 < Tt) {
            const int u = t - 256;
            #pragma unroll
            for (int s = 0; s < 2; s++) {
                int e = u + s * 256;
                sm.xs[e] = pf_x[s]; sm.ms[e] = pf_m[s];
            }
            int j = u & 63, rp = u >> 6;
            *(float2*)(sm.alp + rp * 128 + j * 2) = make_float2(pf_a0, pf_a1);
        }
        __syncthreads();
    }

    // ---- final: y = h @ out_W + out_b ----
    {
        int w = t >> 5, lane = t & 31;
        if (w < MB) {
            float s = 0.f;
            for (int k = lane; k < Hh; k += 32)
                s += sm.hp[(w >> 1) * 512 + k * 2 + (w & 1)] * outW[k];
            #pragma unroll
            for (int o = 16; o > 0; o >>= 1)
                s += __shfl_down_sync(0xffffffffu, s, o);
            if (lane == 0) yout[b0 + w] = s + outB[0];
        }
    }
}

// ================================ launcher ================================

extern "C" void kernel_launch(void* const* d_in, const int* in_sizes, int n_in,
                              void* d_out, int out_size) {
    const float* values = (const float*)d_in[0];
    const float* masks  = (const float*)d_in[1];
    const float* deltas = (const float*)d_in[2];
    const float* tdhW   = (const float*)d_in[3];
    const float* tdhB   = (const float*)d_in[4];
    const float* tdxW   = (const float*)d_in[5];
    const float* tdxB   = (const float*)d_in[6];
    const float* histW  = (const float*)d_in[7];
    const float* histB  = (const float*)d_in[8];
    const float* frW    = (const float*)d_in[9];
    const float* frB    = (const float*)d_in[10];
    const float* wcW    = (const float*)d_in[11];
    const float* wcB    = (const float*)d_in[12];
    const float* lstmK  = (const float*)d_in[13];
    const float* lstmRK = (const float*)d_in[14];
    const float* lstmB  = (const float*)d_in[15];
    const float* outW   = (const float*)d_in[16];
    const float* outB   = (const float*)d_in[17];

    float* yout   = (float*)d_out;       // y_h [B,1] first
    float* impout = yout + Bsz;          // imputations [B,T,D]

    transpose_kernel<<<(Hh * Dd + Dd * Dd + 255) / 256, 256>>>(tdhW, tdxW);
    pre_ga_kernel<<<Bsz * Tt / 8, 256>>>(deltas, masks, tdhB, tdxB, wcW, wcB);

    static int zsm = (64 * 256 + 256 + 16 * 128) * 4;   // ~73 KB
    cudaFuncSetAttribute(pre_z_kernel, cudaFuncAttributeMaxDynamicSharedMemorySize, zsm);
    pre_z_kernel<<<dim3(4, Bsz / 2), 256, zsm>>>(masks, lstmK, lstmB);

    cudaFuncSetAttribute(rits_kernel, cudaFuncAttributeMaxDynamicSharedMemorySize,
                         (int)sizeof(Smem));
    rits_kernel<<<GRID, NT, sizeof(Smem)>>>(
        values, masks, histW, histB, frW, frB,
        lstmK, lstmRK, outW, outB, yout, impout);
}